// round 1
// baseline (speedup 1.0000x reference)
#include <cuda_runtime.h>
#include <math.h>

#define N_NODES_MAX 100000
#define NODE_DIM 128
#define EDGE_DIM 48
#define HIDDEN 64
#define IN_DIM (NODE_DIM + EDGE_DIM)   // 176
#define LN_EPS 1e-5f

// ---------------- scratch (device globals; no allocation allowed) ----------
__device__ __align__(16) float g_agg[(size_t)N_NODES_MAX * EDGE_DIM]; // 19.2 MB
__device__ float g_deg[N_NODES_MAX];

// ---------------- kernel 0: zero scratch ----------------------------------
__global__ void zero_kernel(int n_nodes) {
    int total4 = n_nodes * (EDGE_DIM / 4);
    float4 z = make_float4(0.f, 0.f, 0.f, 0.f);
    for (int i = blockIdx.x * blockDim.x + threadIdx.x; i < total4;
         i += gridDim.x * blockDim.x)
        ((float4*)g_agg)[i] = z;
    for (int i = blockIdx.x * blockDim.x + threadIdx.x; i < n_nodes;
         i += gridDim.x * blockDim.x)
        g_deg[i] = 0.f;
}

// ---------------- kernel 1: edge scatter (vector fp32 reduction) -----------
__device__ __forceinline__ void red_add_v4(float* addr, float4 v) {
    asm volatile("red.global.add.v4.f32 [%0], {%1,%2,%3,%4};"
                 :: "l"(addr), "f"(v.x), "f"(v.y), "f"(v.z), "f"(v.w)
                 : "memory");
}

// blockDim = 384 -> 32 edges per block, 12 float4 lanes per edge (48 floats)
__global__ void scatter_kernel(const float4* __restrict__ ef4,
                               const int* __restrict__ recv,
                               int n_edges) {
    int t = blockIdx.x * 384 + threadIdx.x;
    int e = t / 12;
    int q = t - e * 12;
    if (e >= n_edges) return;
    int r = recv[e];
    float4 v = ef4[(size_t)e * 12 + q];
    float* dst = g_agg + (size_t)r * EDGE_DIM + q * 4;
    red_add_v4(dst, v);
    if (q == 0) atomicAdd(&g_deg[r], 1.0f);
}

// ---------------- kernel 2: fused MLP + LayerNorm --------------------------
// blockDim = 256 (8 warps). Each warp processes 4 nodes at a time.
// Lane j computes outputs j and j+32. Weights in smem as float2 pairs
// (W[k][j], W[k][j+32]) so one LDS.64 per k serves both outputs.

#define WARPS_PER_BLOCK 8
#define NODES_PER_WARP 4

// dynamic smem layout (float2 units then floats)
#define SW1_F2 (IN_DIM * 32)     // 5632
#define SW2_F2 (HIDDEN * 32)     // 2048
#define SW3_F2 (HIDDEN * 32)     // 2048
#define SVEC_F2 32               // per bias/gamma/beta array
#define SX_FLOATS (WARPS_PER_BLOCK * NODES_PER_WARP * IN_DIM)   // 5632
#define SH_FLOATS (WARPS_PER_BLOCK * NODES_PER_WARP * HIDDEN)   // 2048
#define MLP_SMEM_BYTES ((SW1_F2 + SW2_F2 + SW3_F2 + 5 * SVEC_F2) * 8 \
                        + (SX_FLOATS + SH_FLOATS) * 4)           // 109,824 B

template <int K>
__device__ __forceinline__ void gemm_step(const float2* __restrict__ W,
                                          const float* r0, const float* r1,
                                          const float* r2, const float* r3,
                                          int lane,
                                          float2& a0, float2& a1,
                                          float2& a2, float2& a3) {
#pragma unroll 4
    for (int k = 0; k < K; k += 4) {
        float4 x0 = *(const float4*)(r0 + k);
        float4 x1 = *(const float4*)(r1 + k);
        float4 x2 = *(const float4*)(r2 + k);
        float4 x3 = *(const float4*)(r3 + k);
        {
            float2 wv = W[(k + 0) * 32 + lane];
            a0.x += x0.x * wv.x; a0.y += x0.x * wv.y;
            a1.x += x1.x * wv.x; a1.y += x1.x * wv.y;
            a2.x += x2.x * wv.x; a2.y += x2.x * wv.y;
            a3.x += x3.x * wv.x; a3.y += x3.x * wv.y;
        }
        {
            float2 wv = W[(k + 1) * 32 + lane];
            a0.x += x0.y * wv.x; a0.y += x0.y * wv.y;
            a1.x += x1.y * wv.x; a1.y += x1.y * wv.y;
            a2.x += x2.y * wv.x; a2.y += x2.y * wv.y;
            a3.x += x3.y * wv.x; a3.y += x3.y * wv.y;
        }
        {
            float2 wv = W[(k + 2) * 32 + lane];
            a0.x += x0.z * wv.x; a0.y += x0.z * wv.y;
            a1.x += x1.z * wv.x; a1.y += x1.z * wv.y;
            a2.x += x2.z * wv.x; a2.y += x2.z * wv.y;
            a3.x += x3.z * wv.x; a3.y += x3.z * wv.y;
        }
        {
            float2 wv = W[(k + 3) * 32 + lane];
            a0.x += x0.w * wv.x; a0.y += x0.w * wv.y;
            a1.x += x1.w * wv.x; a1.y += x1.w * wv.y;
            a2.x += x2.w * wv.x; a2.y += x2.w * wv.y;
            a3.x += x3.w * wv.x; a3.y += x3.w * wv.y;
        }
    }
}

__global__ __launch_bounds__(256, 2)
void mlp_kernel(const float* __restrict__ nf,
                const float* __restrict__ W1, const float* __restrict__ b1,
                const float* __restrict__ W2, const float* __restrict__ b2,
                const float* __restrict__ W3, const float* __restrict__ b3,
                const float* __restrict__ gamma, const float* __restrict__ beta,
                float* __restrict__ out, int n_nodes) {
    extern __shared__ float smem_raw[];
    float2* sW1 = (float2*)smem_raw;
    float2* sW2 = sW1 + SW1_F2;
    float2* sW3 = sW2 + SW2_F2;
    float2* sb1 = sW3 + SW3_F2;
    float2* sb2 = sb1 + SVEC_F2;
    float2* sb3 = sb2 + SVEC_F2;
    float2* sgm = sb3 + SVEC_F2;
    float2* sbt = sgm + SVEC_F2;
    float* sX = (float*)(sbt + SVEC_F2);
    float* sH = sX + SX_FLOATS;

    int tid = threadIdx.x;

    // ---- stage weights as (j, j+32) float2 pairs ----
    for (int idx = tid; idx < SW1_F2; idx += 256) {
        int k = idx >> 5, j = idx & 31;
        sW1[idx] = make_float2(W1[k * 64 + j], W1[k * 64 + j + 32]);
    }
    for (int idx = tid; idx < SW2_F2; idx += 256) {
        int k = idx >> 5, j = idx & 31;
        sW2[idx] = make_float2(W2[k * 64 + j], W2[k * 64 + j + 32]);
        sW3[idx] = make_float2(W3[k * 64 + j], W3[k * 64 + j + 32]);
    }
    if (tid < 32) {
        sb1[tid] = make_float2(b1[tid], b1[tid + 32]);
        sb2[tid] = make_float2(b2[tid], b2[tid + 32]);
        sb3[tid] = make_float2(b3[tid], b3[tid + 32]);
        sgm[tid] = make_float2(gamma[tid], gamma[tid + 32]);
        sbt[tid] = make_float2(beta[tid], beta[tid + 32]);
    }
    __syncthreads();

    int warp = blockIdx.x * WARPS_PER_BLOCK + (tid >> 5);
    int lane = tid & 31;
    int nwarps = gridDim.x * WARPS_PER_BLOCK;
    float* sXw = sX + (tid >> 5) * NODES_PER_WARP * IN_DIM;
    float* sHw = sH + (tid >> 5) * NODES_PER_WARP * HIDDEN;
    const float4* nf4 = (const float4*)nf;
    const float4* agg4 = (const float4*)g_agg;

    for (int n0 = warp * NODES_PER_WARP; n0 < n_nodes;
         n0 += nwarps * NODES_PER_WARP) {
        // ---- assemble x = [node_features | agg/deg] for 4 nodes ----
#pragma unroll
        for (int s = 0; s < NODES_PER_WARP; s++) {
            int n = min(n0 + s, n_nodes - 1);
            float* row = sXw + s * IN_DIM;
            float4 v = nf4[(size_t)n * 32 + lane];
            *(float4*)(row + lane * 4) = v;
            if (lane < 12) {
                float4 a = agg4[(size_t)n * 12 + lane];
                float inv = 1.0f / fmaxf(g_deg[n], 1.0f);
                a.x *= inv; a.y *= inv; a.z *= inv; a.w *= inv;
                *(float4*)(row + NODE_DIM + lane * 4) = a;
            }
        }
        __syncwarp();

        // ---- layer 1: 176 -> 64, ReLU ----
        float2 a0 = sb1[lane], a1 = a0, a2 = a0, a3 = a0;
        gemm_step<IN_DIM>(sW1, sXw, sXw + IN_DIM, sXw + 2 * IN_DIM,
                          sXw + 3 * IN_DIM, lane, a0, a1, a2, a3);
        sHw[0 * HIDDEN + lane]      = fmaxf(a0.x, 0.f);
        sHw[0 * HIDDEN + lane + 32] = fmaxf(a0.y, 0.f);
        sHw[1 * HIDDEN + lane]      = fmaxf(a1.x, 0.f);
        sHw[1 * HIDDEN + lane + 32] = fmaxf(a1.y, 0.f);
        sHw[2 * HIDDEN + lane]      = fmaxf(a2.x, 0.f);
        sHw[2 * HIDDEN + lane + 32] = fmaxf(a2.y, 0.f);
        sHw[3 * HIDDEN + lane]      = fmaxf(a3.x, 0.f);
        sHw[3 * HIDDEN + lane + 32] = fmaxf(a3.y, 0.f);
        __syncwarp();

        // ---- layer 2: 64 -> 64, ReLU ----
        a0 = sb2[lane]; a1 = a0; a2 = a0; a3 = a0;
        gemm_step<HIDDEN>(sW2, sHw, sHw + HIDDEN, sHw + 2 * HIDDEN,
                          sHw + 3 * HIDDEN, lane, a0, a1, a2, a3);
        __syncwarp();
        sHw[0 * HIDDEN + lane]      = fmaxf(a0.x, 0.f);
        sHw[0 * HIDDEN + lane + 32] = fmaxf(a0.y, 0.f);
        sHw[1 * HIDDEN + lane]      = fmaxf(a1.x, 0.f);
        sHw[1 * HIDDEN + lane + 32] = fmaxf(a1.y, 0.f);
        sHw[2 * HIDDEN + lane]      = fmaxf(a2.x, 0.f);
        sHw[2 * HIDDEN + lane + 32] = fmaxf(a2.y, 0.f);
        sHw[3 * HIDDEN + lane]      = fmaxf(a3.x, 0.f);
        sHw[3 * HIDDEN + lane + 32] = fmaxf(a3.y, 0.f);
        __syncwarp();

        // ---- layer 3: 64 -> 64 (no ReLU) ----
        a0 = sb3[lane]; a1 = a0; a2 = a0; a3 = a0;
        gemm_step<HIDDEN>(sW3, sHw, sHw + HIDDEN, sHw + 2 * HIDDEN,
                          sHw + 3 * HIDDEN, lane, a0, a1, a2, a3);

        // ---- LayerNorm + write ----
        float2 g = sgm[lane], bt = sbt[lane];
        float2 accs[4] = {a0, a1, a2, a3};
#pragma unroll
        for (int s = 0; s < NODES_PER_WARP; s++) {
            float o0 = accs[s].x, o1 = accs[s].y;
            float sum = o0 + o1;
            float sq = o0 * o0 + o1 * o1;
#pragma unroll
            for (int off = 16; off > 0; off >>= 1) {
                sum += __shfl_xor_sync(0xFFFFFFFFu, sum, off);
                sq  += __shfl_xor_sync(0xFFFFFFFFu, sq, off);
            }
            float mu = sum * (1.0f / 64.0f);
            float var = sq * (1.0f / 64.0f) - mu * mu;
            float inv = rsqrtf(var + LN_EPS);
            int n = n0 + s;
            if (n < n_nodes) {
                out[(size_t)n * 64 + lane]      = (o0 - mu) * inv * g.x + bt.x;
                out[(size_t)n * 64 + lane + 32] = (o1 - mu) * inv * g.y + bt.y;
            }
        }
        __syncwarp();
    }
}

// ---------------- launcher -------------------------------------------------
extern "C" void kernel_launch(void* const* d_in, const int* in_sizes, int n_in,
                              void* d_out, int out_size) {
    const float* nf   = (const float*)d_in[0];
    const float* ef   = (const float*)d_in[1];
    const int* recv   = (const int*)d_in[2];
    // d_in[3] = num_nodes (scalar), unused — derive from sizes
    const float* W1   = (const float*)d_in[4];
    const float* b1   = (const float*)d_in[5];
    const float* W2   = (const float*)d_in[6];
    const float* b2   = (const float*)d_in[7];
    const float* W3   = (const float*)d_in[8];
    const float* b3   = (const float*)d_in[9];
    const float* gam  = (const float*)d_in[10];
    const float* bet  = (const float*)d_in[11];
    float* out = (float*)d_out;

    int n_nodes = in_sizes[0] / NODE_DIM;
    int n_edges = in_sizes[2];
    if (n_nodes > N_NODES_MAX) n_nodes = N_NODES_MAX;

    zero_kernel<<<2048, 256>>>(n_nodes);

    int sblocks = (n_edges + 31) / 32;
    scatter_kernel<<<sblocks, 384>>>((const float4*)ef, recv, n_edges);

    cudaFuncSetAttribute(mlp_kernel,
                         cudaFuncAttributeMaxDynamicSharedMemorySize,
                         MLP_SMEM_BYTES);
    mlp_kernel<<<296, 256, MLP_SMEM_BYTES>>>(nf, W1, b1, W2, b2, W3, b3,
                                             gam, bet, out, n_nodes);
}